// round 4
// baseline (speedup 1.0000x reference)
#include <cuda_runtime.h>
#include <cstdint>

// ---------------- problem constants ----------------
#define MAXN    100000
#define MAXE    3200000
#define NFEAT   512
#define HID     64
#define NCLASS  64
#define ALPHA   0.1f
#define NITER   10
#define SCAN_BLK 1024

typedef unsigned long long ull;

// ---------------- static device scratch ----------------
__device__ float g_z0[MAXN * NCLASS];
__device__ float g_za[MAXN * NCLASS];
__device__ float g_zb[MAXN * NCLASS];
__device__ int   g_rowptr[MAXN + 1];
__device__ int   g_cursor[MAXN];
__device__ int   g_bsums[128];
__device__ int2  g_edges[MAXE];

// ---------------- packed f32x2 helpers ----------------
__device__ __forceinline__ void fma2(ull& d, ull a, ull b) {
    asm("fma.rn.f32x2 %0, %1, %2, %0;" : "+l"(d) : "l"(a), "l"(b));
}
__device__ __forceinline__ ull pack2(float lo, float hi) {
    ull r; asm("mov.b64 %0, {%1, %2};" : "=l"(r) : "f"(lo), "f"(hi)); return r;
}
__device__ __forceinline__ float2 unpack2(ull v) {
    float2 f; asm("mov.b64 {%0, %1}, %2;" : "=f"(f.x), "=f"(f.y) : "l"(v)); return f;
}

// =================================================================
// Fused GEMM: z0[n,64] = relu(x[n,512] @ W1[512,64]) @ W2[64,64]
// BM=128, BN=64, BK=32, 256 threads (16x16), TM=8 (4 row-pairs), TN=4.
// Inner loop uses fma.rn.f32x2: A stored [k][m] (row-pairs contiguous ->
// direct 64-bit smem loads), B stored value-duplicated {b,b}.
// =================================================================
#define AS_TILE (32 * 132)      // [k][m] padded
#define BS_TILE (32 * 128)      // [k][2*n] duplicated
// phase 2 overlays: Hs = 64*132 = 8448 (== 2*AS_TILE), Ws = 64*128 = 8192 (== 2*BS_TILE)
#define SMEM_FLOATS (2 * AS_TILE + 2 * BS_TILE)   // 16640 floats = 66560 B

__global__ __launch_bounds__(256) void gemm_fused(
    const float* __restrict__ A, const float* __restrict__ W1,
    const float* __restrict__ W2, float* __restrict__ C, int n)
{
    extern __shared__ float sm[];
    float* As = sm;                 // [2][AS_TILE]
    float* Bs = sm + 2 * AS_TILE;   // [2][BS_TILE]
    float* Hs = sm;                 // phase 2: [64][132]
    float* Ws = sm + 2 * AS_TILE;   // phase 2: [64][128] duplicated

    const int tid = threadIdx.x;
    const int tx  = tid & 15;
    const int ty  = tid >> 4;
    const int bm  = blockIdx.x * 128;

    ull acc[4][4];
#pragma unroll
    for (int p = 0; p < 4; p++)
#pragma unroll
        for (int c = 0; c < 4; c++) acc[p][c] = 0ull;

    // ---- load tile 0 ----
    {
#pragma unroll
        for (int it = 0; it < 4; it++) {
            int idx = it * 256 + tid;
            int r   = idx >> 3;
            int c4  = idx & 7;
            int row = bm + r;
            float4 v = make_float4(0.f, 0.f, 0.f, 0.f);
            if (row < n)
                v = *reinterpret_cast<const float4*>(A + (size_t)row * NFEAT + c4 * 4);
            As[(c4 * 4 + 0) * 132 + r] = v.x;
            As[(c4 * 4 + 1) * 132 + r] = v.y;
            As[(c4 * 4 + 2) * 132 + r] = v.z;
            As[(c4 * 4 + 3) * 132 + r] = v.w;
        }
#pragma unroll
        for (int it = 0; it < 2; it++) {
            int idx = it * 256 + tid;
            int kr  = idx >> 4;
            int c4  = idx & 15;
            float4 v = *reinterpret_cast<const float4*>(W1 + (size_t)kr * HID + c4 * 4);
            float4 d0 = make_float4(v.x, v.x, v.y, v.y);
            float4 d1 = make_float4(v.z, v.z, v.w, v.w);
            *reinterpret_cast<float4*>(&Bs[kr * 128 + c4 * 8])     = d0;
            *reinterpret_cast<float4*>(&Bs[kr * 128 + c4 * 8 + 4]) = d1;
        }
    }
    __syncthreads();

    // ---- 16 k-tiles, double buffered ----
    for (int t = 0; t < 16; t++) {
        float4 pa[4];
        float4 pb[2];
        const bool more = (t < 15);
        if (more) {
            int kt = (t + 1) * 32;
#pragma unroll
            for (int it = 0; it < 4; it++) {
                int idx = it * 256 + tid;
                int r   = idx >> 3;
                int c4  = idx & 7;
                int row = bm + r;
                pa[it] = make_float4(0.f, 0.f, 0.f, 0.f);
                if (row < n)
                    pa[it] = *reinterpret_cast<const float4*>(A + (size_t)row * NFEAT + kt + c4 * 4);
            }
#pragma unroll
            for (int it = 0; it < 2; it++) {
                int idx = it * 256 + tid;
                int kr  = idx >> 4;
                int c4  = idx & 15;
                pb[it] = *reinterpret_cast<const float4*>(W1 + (size_t)(kt + kr) * HID + c4 * 4);
            }
        }

        const float* AsB = As + (t & 1) * AS_TILE;
        const float* BsB = Bs + (t & 1) * BS_TILE;
#pragma unroll
        for (int k = 0; k < 32; k++) {
            const ull* Ar = reinterpret_cast<const ull*>(&AsB[k * 132 + ty * 8]);
            const ull* Br = reinterpret_cast<const ull*>(&BsB[k * 128 + tx * 8]);
            ull a0 = Ar[0], a1 = Ar[1], a2 = Ar[2], a3 = Ar[3];
            ull b0 = Br[0], b1 = Br[1], b2 = Br[2], b3 = Br[3];
            fma2(acc[0][0], a0, b0); fma2(acc[0][1], a0, b1);
            fma2(acc[0][2], a0, b2); fma2(acc[0][3], a0, b3);
            fma2(acc[1][0], a1, b0); fma2(acc[1][1], a1, b1);
            fma2(acc[1][2], a1, b2); fma2(acc[1][3], a1, b3);
            fma2(acc[2][0], a2, b0); fma2(acc[2][1], a2, b1);
            fma2(acc[2][2], a2, b2); fma2(acc[2][3], a2, b3);
            fma2(acc[3][0], a3, b0); fma2(acc[3][1], a3, b1);
            fma2(acc[3][2], a3, b2); fma2(acc[3][3], a3, b3);
        }

        if (more) {
            float* AsN = As + ((t + 1) & 1) * AS_TILE;
            float* BsN = Bs + ((t + 1) & 1) * BS_TILE;
#pragma unroll
            for (int it = 0; it < 4; it++) {
                int idx = it * 256 + tid;
                int r   = idx >> 3;
                int c4  = idx & 7;
                AsN[(c4 * 4 + 0) * 132 + r] = pa[it].x;
                AsN[(c4 * 4 + 1) * 132 + r] = pa[it].y;
                AsN[(c4 * 4 + 2) * 132 + r] = pa[it].z;
                AsN[(c4 * 4 + 3) * 132 + r] = pa[it].w;
            }
#pragma unroll
            for (int it = 0; it < 2; it++) {
                int idx = it * 256 + tid;
                int kr  = idx >> 4;
                int c4  = idx & 15;
                float4 v = pb[it];
                float4 d0 = make_float4(v.x, v.x, v.y, v.y);
                float4 d1 = make_float4(v.z, v.z, v.w, v.w);
                *reinterpret_cast<float4*>(&BsN[kr * 128 + c4 * 8])     = d0;
                *reinterpret_cast<float4*>(&BsN[kr * 128 + c4 * 8 + 4]) = d1;
            }
            __syncthreads();
        }
    }

    // ---- phase 2: z0 = relu(h) @ W2 ----
    __syncthreads();   // all reads of As/Bs done before overlay

    // relu + store h into Hs[k][m] (k = hid index, row-pairs contiguous)
#pragma unroll
    for (int p = 0; p < 4; p++)
#pragma unroll
        for (int c = 0; c < 4; c++) {
            float2 v = unpack2(acc[p][c]);
            v.x = fmaxf(v.x, 0.f);
            v.y = fmaxf(v.y, 0.f);
            *reinterpret_cast<ull*>(&Hs[(tx * 4 + c) * 132 + ty * 8 + 2 * p]) =
                pack2(v.x, v.y);
        }
    // W2 -> Ws duplicated
#pragma unroll
    for (int it = 0; it < 4; it++) {
        int idx = it * 256 + tid;
        int kr  = idx >> 4;
        int c4  = idx & 15;
        float4 v = *reinterpret_cast<const float4*>(W2 + (size_t)kr * NCLASS + c4 * 4);
        float4 d0 = make_float4(v.x, v.x, v.y, v.y);
        float4 d1 = make_float4(v.z, v.z, v.w, v.w);
        *reinterpret_cast<float4*>(&Ws[kr * 128 + c4 * 8])     = d0;
        *reinterpret_cast<float4*>(&Ws[kr * 128 + c4 * 8 + 4]) = d1;
    }
    __syncthreads();

    ull acc2[4][4];
#pragma unroll
    for (int p = 0; p < 4; p++)
#pragma unroll
        for (int c = 0; c < 4; c++) acc2[p][c] = 0ull;

#pragma unroll 8
    for (int k = 0; k < 64; k++) {
        const ull* Ar = reinterpret_cast<const ull*>(&Hs[k * 132 + ty * 8]);
        const ull* Br = reinterpret_cast<const ull*>(&Ws[k * 128 + tx * 8]);
        ull a0 = Ar[0], a1 = Ar[1], a2 = Ar[2], a3 = Ar[3];
        ull b0 = Br[0], b1 = Br[1], b2 = Br[2], b3 = Br[3];
        fma2(acc2[0][0], a0, b0); fma2(acc2[0][1], a0, b1);
        fma2(acc2[0][2], a0, b2); fma2(acc2[0][3], a0, b3);
        fma2(acc2[1][0], a1, b0); fma2(acc2[1][1], a1, b1);
        fma2(acc2[1][2], a1, b2); fma2(acc2[1][3], a1, b3);
        fma2(acc2[2][0], a2, b0); fma2(acc2[2][1], a2, b1);
        fma2(acc2[2][2], a2, b2); fma2(acc2[2][3], a2, b3);
        fma2(acc2[3][0], a3, b0); fma2(acc2[3][1], a3, b1);
        fma2(acc2[3][2], a3, b2); fma2(acc2[3][3], a3, b3);
    }

    // write z0: rows bm + ty*8 + 2p (+1), cols tx*4 + c
#pragma unroll
    for (int p = 0; p < 4; p++) {
        int r0 = bm + ty * 8 + 2 * p;
        float2 v0 = unpack2(acc2[p][0]);
        float2 v1 = unpack2(acc2[p][1]);
        float2 v2 = unpack2(acc2[p][2]);
        float2 v3 = unpack2(acc2[p][3]);
        if (r0 < n)
            *reinterpret_cast<float4*>(C + (size_t)r0 * NCLASS + tx * 4) =
                make_float4(v0.x, v1.x, v2.x, v3.x);
        if (r0 + 1 < n)
            *reinterpret_cast<float4*>(C + (size_t)(r0 + 1) * NCLASS + tx * 4) =
                make_float4(v0.y, v1.y, v2.y, v3.y);
    }
}

// =================================================================
// CSR construction
// =================================================================
__global__ __launch_bounds__(256) void zero_hist(int* __restrict__ cnt, int n)
{
    int i = blockIdx.x * 256 + threadIdx.x;
    if (i < n) cnt[i] = 0;
}

__global__ __launch_bounds__(256) void hist_dst(
    const int* __restrict__ dst, int* __restrict__ cnt, int e)
{
    int i = blockIdx.x * 256 + threadIdx.x;
    if (i < e) atomicAdd(&cnt[dst[i]], 1);
}

__global__ __launch_bounds__(SCAN_BLK) void scan1(
    const int* __restrict__ cnt, int* __restrict__ rowptr,
    int* __restrict__ bsums, int n)
{
    __shared__ int sh[SCAN_BLK];
    int t = threadIdx.x;
    int i = blockIdx.x * SCAN_BLK + t;
    int v = (i < n) ? cnt[i] : 0;
    sh[t] = v;
    __syncthreads();
#pragma unroll
    for (int off = 1; off < SCAN_BLK; off <<= 1) {
        int x = (t >= off) ? sh[t - off] : 0;
        __syncthreads();
        sh[t] += x;
        __syncthreads();
    }
    int incl = sh[t];
    if (i < n) rowptr[i] = incl - v;
    if (t == SCAN_BLK - 1) bsums[blockIdx.x] = incl;
}

__global__ __launch_bounds__(128) void scan2(int* __restrict__ bsums, int nb)
{
    __shared__ int sh[128];
    int t = threadIdx.x;
    int v = (t < nb) ? bsums[t] : 0;
    sh[t] = v;
    __syncthreads();
#pragma unroll
    for (int off = 1; off < 128; off <<= 1) {
        int x = (t >= off) ? sh[t - off] : 0;
        __syncthreads();
        sh[t] += x;
        __syncthreads();
    }
    if (t < nb) bsums[t] = sh[t] - v;
}

__global__ __launch_bounds__(256) void scan3(
    int* __restrict__ rowptr, int* __restrict__ cursor,
    const int* __restrict__ bsums, int n, int e)
{
    int i = blockIdx.x * 256 + threadIdx.x;
    if (i < n) {
        int v = rowptr[i] + bsums[i >> 10];
        rowptr[i] = v;
        cursor[i] = v;
    }
    if (i == n) rowptr[n] = e;
}

__global__ __launch_bounds__(256) void build_edges(
    const int* __restrict__ src, const int* __restrict__ dst,
    const float* __restrict__ ew, int* __restrict__ cursor,
    int2* __restrict__ edges, int e)
{
    int i = blockIdx.x * 256 + threadIdx.x;
    if (i < e) {
        int d = dst[i];
        int pos = atomicAdd(&cursor[d], 1);
        edges[pos] = make_int2(src[i], __float_as_int(ew[i]));
    }
}

// =================================================================
// gather: one warp per dst node; half-warp per edge; 4-deep unroll.
// =================================================================
template<bool LAST>
__global__ __launch_bounds__(256) void gather_nodes(
    const int2* __restrict__ edges, const int* __restrict__ rowptr,
    const float* __restrict__ zin, const float* __restrict__ z0,
    float* __restrict__ zout, int n)
{
    int warp = (blockIdx.x * 256 + threadIdx.x) >> 5;
    if (warp >= n) return;
    int lane = threadIdx.x & 31;
    int half = lane >> 4;
    int c4   = lane & 15;

    int beg = __ldg(&rowptr[warp]);
    int end = __ldg(&rowptr[warp + 1]);

    float4 acc = make_float4(0.f, 0.f, 0.f, 0.f);

    int i = beg + half;
    // 4 edges per half in flight
    for (; i + 6 < end; i += 8) {
        int2 e0 = __ldg(&edges[i]);
        int2 e1 = __ldg(&edges[i + 2]);
        int2 e2 = __ldg(&edges[i + 4]);
        int2 e3 = __ldg(&edges[i + 6]);
        float4 v0 = __ldg(reinterpret_cast<const float4*>(zin + (size_t)e0.x * NCLASS) + c4);
        float4 v1 = __ldg(reinterpret_cast<const float4*>(zin + (size_t)e1.x * NCLASS) + c4);
        float4 v2 = __ldg(reinterpret_cast<const float4*>(zin + (size_t)e2.x * NCLASS) + c4);
        float4 v3 = __ldg(reinterpret_cast<const float4*>(zin + (size_t)e3.x * NCLASS) + c4);
        float w0 = __int_as_float(e0.y), w1 = __int_as_float(e1.y);
        float w2 = __int_as_float(e2.y), w3 = __int_as_float(e3.y);
        acc.x = fmaf(w0, v0.x, acc.x); acc.y = fmaf(w0, v0.y, acc.y);
        acc.z = fmaf(w0, v0.z, acc.z); acc.w = fmaf(w0, v0.w, acc.w);
        acc.x = fmaf(w1, v1.x, acc.x); acc.y = fmaf(w1, v1.y, acc.y);
        acc.z = fmaf(w1, v1.z, acc.z); acc.w = fmaf(w1, v1.w, acc.w);
        acc.x = fmaf(w2, v2.x, acc.x); acc.y = fmaf(w2, v2.y, acc.y);
        acc.z = fmaf(w2, v2.z, acc.z); acc.w = fmaf(w2, v2.w, acc.w);
        acc.x = fmaf(w3, v3.x, acc.x); acc.y = fmaf(w3, v3.y, acc.y);
        acc.z = fmaf(w3, v3.z, acc.z); acc.w = fmaf(w3, v3.w, acc.w);
    }
    for (; i < end; i += 2) {
        int2 e0 = __ldg(&edges[i]);
        float w0 = __int_as_float(e0.y);
        float4 v0 = __ldg(reinterpret_cast<const float4*>(zin + (size_t)e0.x * NCLASS) + c4);
        acc.x = fmaf(w0, v0.x, acc.x);
        acc.y = fmaf(w0, v0.y, acc.y);
        acc.z = fmaf(w0, v0.z, acc.z);
        acc.w = fmaf(w0, v0.w, acc.w);
    }

    const unsigned FULL = 0xFFFFFFFFu;
    acc.x += __shfl_xor_sync(FULL, acc.x, 16);
    acc.y += __shfl_xor_sync(FULL, acc.y, 16);
    acc.z += __shfl_xor_sync(FULL, acc.z, 16);
    acc.w += __shfl_xor_sync(FULL, acc.w, 16);

    float4 z0v = __ldg(reinterpret_cast<const float4*>(z0 + (size_t)warp * NCLASS) + c4);
    acc.x = fmaf(ALPHA, z0v.x, acc.x);
    acc.y = fmaf(ALPHA, z0v.y, acc.y);
    acc.z = fmaf(ALPHA, z0v.z, acc.z);
    acc.w = fmaf(ALPHA, z0v.w, acc.w);

    if (!LAST) {
        if (half == 0)
            reinterpret_cast<float4*>(zout + (size_t)warp * NCLASS)[c4] = acc;
    } else {
        float m = fmaxf(fmaxf(acc.x, acc.y), fmaxf(acc.z, acc.w));
#pragma unroll
        for (int o = 8; o > 0; o >>= 1)
            m = fmaxf(m, __shfl_xor_sync(FULL, m, o));
        float s = __expf(acc.x - m) + __expf(acc.y - m) +
                  __expf(acc.z - m) + __expf(acc.w - m);
#pragma unroll
        for (int o = 8; o > 0; o >>= 1)
            s += __shfl_xor_sync(FULL, s, o);
        float l = m + __logf(s);
        if (half == 0) {
            float4 r = make_float4(acc.x - l, acc.y - l, acc.z - l, acc.w - l);
            reinterpret_cast<float4*>(zout + (size_t)warp * NCLASS)[c4] = r;
        }
    }
}

// =================================================================
// launch: GEMM chain on side stream, CSR on capture stream, join.
// =================================================================
extern "C" void kernel_launch(void* const* d_in, const int* in_sizes, int n_in,
                              void* d_out, int out_size)
{
    const float* x   = (const float*)d_in[0];
    const int*   ei  = (const int*)  d_in[1];
    const float* ew  = (const float*)d_in[2];
    const float* W1  = (const float*)d_in[3];
    const float* W2  = (const float*)d_in[4];
    float*       out = (float*)d_out;

    const int n = in_sizes[0] / NFEAT;
    const int e = in_sizes[2];
    const int* src = ei;
    const int* dst = ei + e;

    float* z0  = nullptr; cudaGetSymbolAddress((void**)&z0,  g_z0);
    float* za  = nullptr; cudaGetSymbolAddress((void**)&za,  g_za);
    float* zb  = nullptr; cudaGetSymbolAddress((void**)&zb,  g_zb);
    int*   rp  = nullptr; cudaGetSymbolAddress((void**)&rp,  g_rowptr);
    int*   cur = nullptr; cudaGetSymbolAddress((void**)&cur, g_cursor);
    int*   bs  = nullptr; cudaGetSymbolAddress((void**)&bs,  g_bsums);
    int2*  edg = nullptr; cudaGetSymbolAddress((void**)&edg, g_edges);

    static cudaStream_t sG = nullptr;
    static cudaEvent_t  evF = nullptr, evG = nullptr;
    if (sG == nullptr) {
        cudaStreamCreateWithFlags(&sG, cudaStreamNonBlocking);
        cudaEventCreateWithFlags(&evF, cudaEventDisableTiming);
        cudaEventCreateWithFlags(&evG, cudaEventDisableTiming);
        cudaFuncSetAttribute(gemm_fused,
            cudaFuncAttributeMaxDynamicSharedMemorySize, SMEM_FLOATS * 4);
    }

    // ---- fork: GEMM chain on sG ----
    cudaEventRecord(evF, 0);
    cudaStreamWaitEvent(sG, evF, 0);
    gemm_fused<<<(n + 127) / 128, 256, SMEM_FLOATS * 4, sG>>>(x, W1, W2, z0, n);
    cudaEventRecord(evG, sG);

    // ---- CSR build on capture (default) stream ----
    zero_hist<<<(n + 255) / 256, 256>>>(cur, n);
    hist_dst<<<(e + 255) / 256, 256>>>(dst, cur, e);
    int nb = (n + SCAN_BLK - 1) / SCAN_BLK;
    scan1<<<nb, SCAN_BLK>>>(cur, rp, bs, n);
    scan2<<<1, 128>>>(bs, nb);
    scan3<<<(n + 256) / 256, 256>>>(rp, cur, bs, n, e);
    build_edges<<<(e + 255) / 256, 256>>>(src, dst, ew, cur, edg, e);

    // ---- join ----
    cudaStreamWaitEvent(0, evG, 0);

    // ---- APPNP power iteration (gather form) ----
    const int gblocks = (n * 32 + 255) / 256;
    const float* zin = z0;
    for (int it = 0; it < NITER - 1; it++) {
        float* zout = (it & 1) ? zb : za;
        gather_nodes<false><<<gblocks, 256>>>(edg, rp, zin, z0, zout, n);
        zin = zout;
    }
    gather_nodes<true><<<gblocks, 256>>>(edg, rp, zin, z0, out, n);
}

// round 5
// speedup vs baseline: 1.2705x; 1.2705x over previous
#include <cuda_runtime.h>
#include <cuda_fp16.h>
#include <cstdint>

// ---------------- problem constants ----------------
#define MAXN    100000
#define MAXE    3200000
#define NFEAT   512
#define HID     64
#define NCLASS  64
#define ALPHA   0.1f
#define NITER   10
#define SCAN_BLK 1024

// ---------------- static device scratch ----------------
__device__ float  g_z0[MAXN * NCLASS];     // fp32 base prediction
__device__ __half g_ya[MAXN * NCLASS];     // fp16 scaled z ping
__device__ __half g_yb[MAXN * NCLASS];     // fp16 scaled z pong
__device__ int    g_rowptr[MAXN + 1];
__device__ int    g_cursor[MAXN];
__device__ int    g_bsums[128];
__device__ int2   g_edges[MAXE];

// =================================================================
// Fused GEMM: z0[n,64] = relu(x[n,512] @ W1[512,64]) @ W2[64,64]
// (round-3 scalar version: BM=128,BN=64,BK=32, 256thr, TM=8,TN=4,
//  double-buffered smem, phase-2 overlay)
// =================================================================
#define AS_TILE (32 * 132)
#define BS_TILE (32 * 64)
#define HS_SIZE (128 * 68)
#define SMEM_FLOATS 12800

__global__ __launch_bounds__(256) void gemm_fused(
    const float* __restrict__ A, const float* __restrict__ W1,
    const float* __restrict__ W2, float* __restrict__ C, int n)
{
    extern __shared__ float sm[];
    float* As = sm;
    float* Bs = sm + 2 * AS_TILE;
    float* Hs = sm;
    float* Ws = sm + HS_SIZE;

    const int tid = threadIdx.x;
    const int tx  = tid & 15;
    const int ty  = tid >> 4;
    const int bm  = blockIdx.x * 128;

    float acc[8][4];
#pragma unroll
    for (int i = 0; i < 8; i++)
#pragma unroll
        for (int j = 0; j < 4; j++) acc[i][j] = 0.0f;

    {
#pragma unroll
        for (int it = 0; it < 4; it++) {
            int idx = it * 256 + tid;
            int r   = idx >> 3;
            int c4  = idx & 7;
            int row = bm + r;
            float4 v = make_float4(0.f, 0.f, 0.f, 0.f);
            if (row < n)
                v = *reinterpret_cast<const float4*>(A + (size_t)row * NFEAT + c4 * 4);
            As[(c4 * 4 + 0) * 132 + r] = v.x;
            As[(c4 * 4 + 1) * 132 + r] = v.y;
            As[(c4 * 4 + 2) * 132 + r] = v.z;
            As[(c4 * 4 + 3) * 132 + r] = v.w;
        }
#pragma unroll
        for (int it = 0; it < 2; it++) {
            int idx = it * 256 + tid;
            int kr  = idx >> 4;
            int c4  = idx & 15;
            *reinterpret_cast<float4*>(&Bs[kr * 64 + c4 * 4]) =
                *reinterpret_cast<const float4*>(W1 + (size_t)kr * HID + c4 * 4);
        }
    }
    __syncthreads();

    for (int t = 0; t < 16; t++) {
        float4 pa[4];
        float4 pb[2];
        const bool more = (t < 15);
        if (more) {
            int kt = (t + 1) * 32;
#pragma unroll
            for (int it = 0; it < 4; it++) {
                int idx = it * 256 + tid;
                int r   = idx >> 3;
                int c4  = idx & 7;
                int row = bm + r;
                pa[it] = make_float4(0.f, 0.f, 0.f, 0.f);
                if (row < n)
                    pa[it] = *reinterpret_cast<const float4*>(A + (size_t)row * NFEAT + kt + c4 * 4);
            }
#pragma unroll
            for (int it = 0; it < 2; it++) {
                int idx = it * 256 + tid;
                int kr  = idx >> 4;
                int c4  = idx & 15;
                pb[it] = *reinterpret_cast<const float4*>(W1 + (size_t)(kt + kr) * HID + c4 * 4);
            }
        }

        const float* AsB = As + (t & 1) * AS_TILE;
        const float* BsB = Bs + (t & 1) * BS_TILE;
#pragma unroll
        for (int k = 0; k < 32; k++) {
            float4 a0 = *reinterpret_cast<const float4*>(&AsB[k * 132 + ty * 8]);
            float4 a1 = *reinterpret_cast<const float4*>(&AsB[k * 132 + ty * 8 + 4]);
            float4 b  = *reinterpret_cast<const float4*>(&BsB[k * 64 + tx * 4]);
            acc[0][0] = fmaf(a0.x, b.x, acc[0][0]); acc[0][1] = fmaf(a0.x, b.y, acc[0][1]);
            acc[0][2] = fmaf(a0.x, b.z, acc[0][2]); acc[0][3] = fmaf(a0.x, b.w, acc[0][3]);
            acc[1][0] = fmaf(a0.y, b.x, acc[1][0]); acc[1][1] = fmaf(a0.y, b.y, acc[1][1]);
            acc[1][2] = fmaf(a0.y, b.z, acc[1][2]); acc[1][3] = fmaf(a0.y, b.w, acc[1][3]);
            acc[2][0] = fmaf(a0.z, b.x, acc[2][0]); acc[2][1] = fmaf(a0.z, b.y, acc[2][1]);
            acc[2][2] = fmaf(a0.z, b.z, acc[2][2]); acc[2][3] = fmaf(a0.z, b.w, acc[2][3]);
            acc[3][0] = fmaf(a0.w, b.x, acc[3][0]); acc[3][1] = fmaf(a0.w, b.y, acc[3][1]);
            acc[3][2] = fmaf(a0.w, b.z, acc[3][2]); acc[3][3] = fmaf(a0.w, b.w, acc[3][3]);
            acc[4][0] = fmaf(a1.x, b.x, acc[4][0]); acc[4][1] = fmaf(a1.x, b.y, acc[4][1]);
            acc[4][2] = fmaf(a1.x, b.z, acc[4][2]); acc[4][3] = fmaf(a1.x, b.w, acc[4][3]);
            acc[5][0] = fmaf(a1.y, b.x, acc[5][0]); acc[5][1] = fmaf(a1.y, b.y, acc[5][1]);
            acc[5][2] = fmaf(a1.y, b.z, acc[5][2]); acc[5][3] = fmaf(a1.y, b.w, acc[5][3]);
            acc[6][0] = fmaf(a1.z, b.x, acc[6][0]); acc[6][1] = fmaf(a1.z, b.y, acc[6][1]);
            acc[6][2] = fmaf(a1.z, b.z, acc[6][2]); acc[6][3] = fmaf(a1.z, b.w, acc[6][3]);
            acc[7][0] = fmaf(a1.w, b.x, acc[7][0]); acc[7][1] = fmaf(a1.w, b.y, acc[7][1]);
            acc[7][2] = fmaf(a1.w, b.z, acc[7][2]); acc[7][3] = fmaf(a1.w, b.w, acc[7][3]);
        }

        if (more) {
            float* AsN = As + ((t + 1) & 1) * AS_TILE;
            float* BsN = Bs + ((t + 1) & 1) * BS_TILE;
#pragma unroll
            for (int it = 0; it < 4; it++) {
                int idx = it * 256 + tid;
                int r   = idx >> 3;
                int c4  = idx & 7;
                AsN[(c4 * 4 + 0) * 132 + r] = pa[it].x;
                AsN[(c4 * 4 + 1) * 132 + r] = pa[it].y;
                AsN[(c4 * 4 + 2) * 132 + r] = pa[it].z;
                AsN[(c4 * 4 + 3) * 132 + r] = pa[it].w;
            }
#pragma unroll
            for (int it = 0; it < 2; it++) {
                int idx = it * 256 + tid;
                int kr  = idx >> 4;
                int c4  = idx & 15;
                *reinterpret_cast<float4*>(&BsN[kr * 64 + c4 * 4]) = pb[it];
            }
            __syncthreads();
        }
    }

    __syncthreads();

#pragma unroll
    for (int i = 0; i < 8; i++) {
        float4 v;
        v.x = fmaxf(acc[i][0], 0.f);
        v.y = fmaxf(acc[i][1], 0.f);
        v.z = fmaxf(acc[i][2], 0.f);
        v.w = fmaxf(acc[i][3], 0.f);
        *reinterpret_cast<float4*>(&Hs[(ty * 8 + i) * 68 + tx * 4]) = v;
    }
#pragma unroll
    for (int it = 0; it < 4; it++) {
        int idx = it * 256 + tid;
        int kr  = idx >> 4;
        int c4  = idx & 15;
        *reinterpret_cast<float4*>(&Ws[kr * 64 + c4 * 4]) =
            *reinterpret_cast<const float4*>(W2 + (size_t)kr * NCLASS + c4 * 4);
    }
    __syncthreads();

    float acc2[8][4];
#pragma unroll
    for (int i = 0; i < 8; i++)
#pragma unroll
        for (int j = 0; j < 4; j++) acc2[i][j] = 0.0f;

#pragma unroll
    for (int k = 0; k < 64; k++) {
        float4 b = *reinterpret_cast<const float4*>(&Ws[k * 64 + tx * 4]);
#pragma unroll
        for (int i = 0; i < 8; i++) {
            float a = Hs[(ty * 8 + i) * 68 + k];
            acc2[i][0] = fmaf(a, b.x, acc2[i][0]);
            acc2[i][1] = fmaf(a, b.y, acc2[i][1]);
            acc2[i][2] = fmaf(a, b.z, acc2[i][2]);
            acc2[i][3] = fmaf(a, b.w, acc2[i][3]);
        }
    }

#pragma unroll
    for (int i = 0; i < 8; i++) {
        int row = bm + ty * 8 + i;
        if (row < n) {
            float4 v = make_float4(acc2[i][0], acc2[i][1], acc2[i][2], acc2[i][3]);
            *reinterpret_cast<float4*>(C + (size_t)row * NCLASS + tx * 4) = v;
        }
    }
}

// =================================================================
// CSR construction
// =================================================================
__global__ __launch_bounds__(256) void zero_hist(int* __restrict__ cnt, int n)
{
    int i = blockIdx.x * 256 + threadIdx.x;
    if (i < n) cnt[i] = 0;
}

__global__ __launch_bounds__(256) void hist_dst(
    const int* __restrict__ dst, int* __restrict__ cnt, int e)
{
    int i = blockIdx.x * 256 + threadIdx.x;
    if (i < e) atomicAdd(&cnt[dst[i]], 1);
}

__global__ __launch_bounds__(SCAN_BLK) void scan1(
    const int* __restrict__ cnt, int* __restrict__ rowptr,
    int* __restrict__ bsums, int n)
{
    __shared__ int sh[SCAN_BLK];
    int t = threadIdx.x;
    int i = blockIdx.x * SCAN_BLK + t;
    int v = (i < n) ? cnt[i] : 0;
    sh[t] = v;
    __syncthreads();
#pragma unroll
    for (int off = 1; off < SCAN_BLK; off <<= 1) {
        int x = (t >= off) ? sh[t - off] : 0;
        __syncthreads();
        sh[t] += x;
        __syncthreads();
    }
    int incl = sh[t];
    if (i < n) rowptr[i] = incl - v;
    if (t == SCAN_BLK - 1) bsums[blockIdx.x] = incl;
}

__global__ __launch_bounds__(128) void scan2(int* __restrict__ bsums, int nb)
{
    __shared__ int sh[128];
    int t = threadIdx.x;
    int v = (t < nb) ? bsums[t] : 0;
    sh[t] = v;
    __syncthreads();
#pragma unroll
    for (int off = 1; off < 128; off <<= 1) {
        int x = (t >= off) ? sh[t - off] : 0;
        __syncthreads();
        sh[t] += x;
        __syncthreads();
    }
    if (t < nb) bsums[t] = sh[t] - v;
}

__global__ __launch_bounds__(256) void scan3(
    int* __restrict__ rowptr, int* __restrict__ cursor,
    const int* __restrict__ bsums, int n, int e)
{
    int i = blockIdx.x * 256 + threadIdx.x;
    if (i < n) {
        int v = rowptr[i] + bsums[i >> 10];
        rowptr[i] = v;
        cursor[i] = v;
    }
    if (i == n) rowptr[n] = e;
}

__global__ __launch_bounds__(256) void build_edges(
    const int* __restrict__ src, const int* __restrict__ dst,
    const float* __restrict__ ew, int* __restrict__ cursor,
    int2* __restrict__ edges, int e)
{
    int i = blockIdx.x * 256 + threadIdx.x;
    if (i < e) {
        int d = dst[i];
        int pos = atomicAdd(&cursor[d], 1);
        edges[pos] = make_int2(src[i], __float_as_int(ew[i]));
    }
}

// =================================================================
// gather (scaled fp16 pipeline): one warp per dst node.
// 4 sub-groups of 8 lanes; each sub-group walks every 4th edge.
// Lane c8 (0..7) covers classes [c8*8, c8*8+8).
//   out = c1 * (sum_e w_e * zin[src_e]) + c0 * z0[d]
// IN_HALF: zin is fp16 row (128B, one LDG.128 per lane)
// LAST:    out fp32 with fused log_softmax, else fp16 store.
// =================================================================
__device__ __forceinline__ void load_row8_h(
    const __half* zin, int node, int c8, float* v)
{
    float4 raw = __ldg(reinterpret_cast<const float4*>(zin + (size_t)node * NCLASS) + c8);
    const __half2* h = reinterpret_cast<const __half2*>(&raw);
#pragma unroll
    for (int j = 0; j < 4; j++) {
        float2 f = __half22float2(h[j]);
        v[2 * j]     = f.x;
        v[2 * j + 1] = f.y;
    }
}
__device__ __forceinline__ void load_row8_f(
    const float* zin, int node, int c8, float* v)
{
    const float4* p = reinterpret_cast<const float4*>(zin + (size_t)node * NCLASS);
    float4 a = __ldg(p + 2 * c8);
    float4 b = __ldg(p + 2 * c8 + 1);
    v[0] = a.x; v[1] = a.y; v[2] = a.z; v[3] = a.w;
    v[4] = b.x; v[5] = b.y; v[6] = b.z; v[7] = b.w;
}

template<bool IN_HALF, bool LAST>
__global__ __launch_bounds__(256) void gather_nodes(
    const int2* __restrict__ edges, const int* __restrict__ rowptr,
    const void* __restrict__ zin_v, const float* __restrict__ z0,
    void* __restrict__ zout_v, float c1, float c0, int n)
{
    int warp = (blockIdx.x * 256 + threadIdx.x) >> 5;
    if (warp >= n) return;
    int lane = threadIdx.x & 31;
    int sub  = lane >> 3;      // 0..3
    int c8   = lane & 7;       // 16B chunk of fp16 row / 32B of fp32 row

    const __half* zin_h = (const __half*)zin_v;
    const float*  zin_f = (const float*)zin_v;

    int beg = __ldg(&rowptr[warp]);
    int end = __ldg(&rowptr[warp + 1]);

    float acc[8];
#pragma unroll
    for (int j = 0; j < 8; j++) acc[j] = 0.f;

    int i = beg + sub;
    // 2 edges per sub-group in flight (8 rows per warp)
    for (; i + 4 < end; i += 8) {
        int2 e0 = __ldg(&edges[i]);
        int2 e1 = __ldg(&edges[i + 4]);
        float v0[8], v1[8];
        if (IN_HALF) { load_row8_h(zin_h, e0.x, c8, v0); load_row8_h(zin_h, e1.x, c8, v1); }
        else         { load_row8_f(zin_f, e0.x, c8, v0); load_row8_f(zin_f, e1.x, c8, v1); }
        float w0 = __int_as_float(e0.y);
        float w1 = __int_as_float(e1.y);
#pragma unroll
        for (int j = 0; j < 8; j++) acc[j] = fmaf(w0, v0[j], acc[j]);
#pragma unroll
        for (int j = 0; j < 8; j++) acc[j] = fmaf(w1, v1[j], acc[j]);
    }
    for (; i < end; i += 4) {
        int2 e0 = __ldg(&edges[i]);
        float v0[8];
        if (IN_HALF) load_row8_h(zin_h, e0.x, c8, v0);
        else         load_row8_f(zin_f, e0.x, c8, v0);
        float w0 = __int_as_float(e0.y);
#pragma unroll
        for (int j = 0; j < 8; j++) acc[j] = fmaf(w0, v0[j], acc[j]);
    }

    // reduce the 4 sub-groups (lanes with equal c8)
    const unsigned FULL = 0xFFFFFFFFu;
#pragma unroll
    for (int j = 0; j < 8; j++) {
        acc[j] += __shfl_xor_sync(FULL, acc[j], 8);
        acc[j] += __shfl_xor_sync(FULL, acc[j], 16);
    }

    // out = c1 * acc + c0 * z0
    float z0v[8];
    load_row8_f(z0, warp, c8, z0v);
    float o[8];
#pragma unroll
    for (int j = 0; j < 8; j++) o[j] = fmaf(c0, z0v[j], c1 * acc[j]);

    if (!LAST) {
        if (sub == 0) {
            __half2 h[4];
#pragma unroll
            for (int j = 0; j < 4; j++)
                h[j] = __floats2half2_rn(o[2 * j], o[2 * j + 1]);
            __half* zo = (__half*)zout_v;
            *(reinterpret_cast<float4*>(zo + (size_t)warp * NCLASS) + c8) =
                *reinterpret_cast<float4*>(h);
        }
    } else {
        // log_softmax over 64 values spread across the 8 c8-lanes
        float m = o[0];
#pragma unroll
        for (int j = 1; j < 8; j++) m = fmaxf(m, o[j]);
#pragma unroll
        for (int off = 1; off < 8; off <<= 1)
            m = fmaxf(m, __shfl_xor_sync(FULL, m, off));
        float s = 0.f;
#pragma unroll
        for (int j = 0; j < 8; j++) s += __expf(o[j] - m);
#pragma unroll
        for (int off = 1; off < 8; off <<= 1)
            s += __shfl_xor_sync(FULL, s, off);
        float l = m + __logf(s);
        if (sub == 0) {
            float* zo = (float*)zout_v;
            float4 r0 = make_float4(o[0] - l, o[1] - l, o[2] - l, o[3] - l);
            float4 r1 = make_float4(o[4] - l, o[5] - l, o[6] - l, o[7] - l);
            float4* p = reinterpret_cast<float4*>(zo + (size_t)warp * NCLASS);
            p[2 * c8]     = r0;
            p[2 * c8 + 1] = r1;
        }
    }
}

// =================================================================
// launch
// =================================================================
extern "C" void kernel_launch(void* const* d_in, const int* in_sizes, int n_in,
                              void* d_out, int out_size)
{
    const float* x   = (const float*)d_in[0];
    const int*   ei  = (const int*)  d_in[1];
    const float* ew  = (const float*)d_in[2];
    const float* W1  = (const float*)d_in[3];
    const float* W2  = (const float*)d_in[4];
    float*       out = (float*)d_out;

    const int n = in_sizes[0] / NFEAT;
    const int e = in_sizes[2];
    const int* src = ei;
    const int* dst = ei + e;

    float*  z0  = nullptr; cudaGetSymbolAddress((void**)&z0,  g_z0);
    __half* ya  = nullptr; cudaGetSymbolAddress((void**)&ya,  g_ya);
    __half* yb  = nullptr; cudaGetSymbolAddress((void**)&yb,  g_yb);
    int*    rp  = nullptr; cudaGetSymbolAddress((void**)&rp,  g_rowptr);
    int*    cur = nullptr; cudaGetSymbolAddress((void**)&cur, g_cursor);
    int*    bs  = nullptr; cudaGetSymbolAddress((void**)&bs,  g_bsums);
    int2*   edg = nullptr; cudaGetSymbolAddress((void**)&edg, g_edges);

    static cudaStream_t sG = nullptr;
    static cudaEvent_t  evF = nullptr, evG = nullptr;
    if (sG == nullptr) {
        cudaStreamCreateWithFlags(&sG, cudaStreamNonBlocking);
        cudaEventCreateWithFlags(&evF, cudaEventDisableTiming);
        cudaEventCreateWithFlags(&evG, cudaEventDisableTiming);
        cudaFuncSetAttribute(gemm_fused,
            cudaFuncAttributeMaxDynamicSharedMemorySize, SMEM_FLOATS * 4);
    }

    // ---- fork: GEMM on side stream ----
    cudaEventRecord(evF, 0);
    cudaStreamWaitEvent(sG, evF, 0);
    gemm_fused<<<(n + 127) / 128, 256, SMEM_FLOATS * 4, sG>>>(x, W1, W2, z0, n);
    cudaEventRecord(evG, sG);

    // ---- CSR build on capture stream ----
    zero_hist<<<(n + 255) / 256, 256>>>(cur, n);
    hist_dst<<<(e + 255) / 256, 256>>>(dst, cur, e);
    int nb = (n + SCAN_BLK - 1) / SCAN_BLK;
    scan1<<<nb, SCAN_BLK>>>(cur, rp, bs, n);
    scan2<<<1, 128>>>(bs, nb);
    scan3<<<(n + 256) / 256, 256>>>(rp, cur, bs, n, e);
    build_edges<<<(e + 255) / 256, 256>>>(src, dst, ew, cur, edg, e);

    // ---- join ----
    cudaStreamWaitEvent(0, evG, 0);

    // ---- APPNP, scaled-fp16 pipeline ----
    // y_t = z_t / 16^t. Scale constants are exact powers of two.
    const float S = 16.0f;
    const int gblocks = (n * 32 + 255) / 256;

    // iter 0: z0 (fp32) -> y1 (fp16):  y1 = (A z0)/S + (ALPHA/S) z0
    gather_nodes<false, false><<<gblocks, 256>>>(
        edg, rp, z0, z0, ya, 1.0f / S, ALPHA / S, n);

    // iters 1..8: y_t -> y_{t+1}
    __half* bufs[2] = { ya, yb };
    float pw = S * S;                 // S^{t+1} at t=1
    for (int t = 1; t <= 8; t++) {
        __half* zin  = bufs[(t + 1) & 1];
        __half* zout = bufs[t & 1];
        gather_nodes<true, false><<<gblocks, 256>>>(
            edg, rp, zin, z0, zout, 1.0f / S, ALPHA / pw, n);
        pw *= S;
    }

    // iter 9: y9 -> z10 fp32 + log_softmax.  z10 = S^9 * (A y9) + ALPHA z0
    float S9 = 1.0f;
    for (int k = 0; k < 9; k++) S9 *= S;
    gather_nodes<true, true><<<gblocks, 256>>>(
        edg, rp, bufs[1], z0, out, S9, ALPHA, n);
}

// round 7
// speedup vs baseline: 1.4806x; 1.1654x over previous
#include <cuda_runtime.h>
#include <cuda_fp16.h>
#include <cuda_bf16.h>
#include <cstdint>

// ---------------- problem constants ----------------
#define MAXN    100000
#define MAXE    3200000
#define NFEAT   512
#define HID     64
#define NCLASS  64
#define ALPHA   0.1f
#define NITER   10
#define SCAN_BLK 1024

// ---------------- static device scratch ----------------
__device__ float  g_z0[MAXN * NCLASS];     // fp32 base prediction
__device__ __half g_ya[MAXN * NCLASS];     // fp16 scaled z ping
__device__ __half g_yb[MAXN * NCLASS];     // fp16 scaled z pong
__device__ int    g_rowptr[MAXN + 1];
__device__ int    g_cursor[MAXN];
__device__ int    g_bsums[128];
__device__ int2   g_edges[MAXE];

// ================= mma.sync helpers (baseline sm_80+, works on sm_103) ====
__device__ __forceinline__ uint32_t smem_u32(const void* p) {
    uint32_t a;
    asm("{ .reg .u64 t; cvta.to.shared.u64 t, %1; cvt.u32.u64 %0, t; }"
        : "=r"(a) : "l"(p));
    return a;
}
__device__ __forceinline__ void ldsm_x4(uint32_t* r, uint32_t addr) {
    asm volatile("ldmatrix.sync.aligned.m8n8.x4.shared.b16 {%0,%1,%2,%3}, [%4];"
                 : "=r"(r[0]), "=r"(r[1]), "=r"(r[2]), "=r"(r[3]) : "r"(addr));
}
__device__ __forceinline__ void ldsm_x4_t(uint32_t* r, uint32_t addr) {
    asm volatile("ldmatrix.sync.aligned.m8n8.x4.trans.shared.b16 {%0,%1,%2,%3}, [%4];"
                 : "=r"(r[0]), "=r"(r[1]), "=r"(r[2]), "=r"(r[3]) : "r"(addr));
}
__device__ __forceinline__ void mma_bf16(
    float* d, const uint32_t* a, const uint32_t* b)
{
    asm volatile(
        "mma.sync.aligned.m16n8k16.row.col.f32.bf16.bf16.f32 "
        "{%0,%1,%2,%3}, {%4,%5,%6,%7}, {%8,%9}, {%0,%1,%2,%3};"
        : "+f"(d[0]), "+f"(d[1]), "+f"(d[2]), "+f"(d[3])
        : "r"(a[0]), "r"(a[1]), "r"(a[2]), "r"(a[3]), "r"(b[0]), "r"(b[1]));
}
// pack two floats into bf16x2 (lo = first)
__device__ __forceinline__ uint32_t pkbf2(float a, float b) {
    __nv_bfloat162 h = __floats2bfloat162_rn(a, b);
    return *reinterpret_cast<uint32_t*>(&h);
}

// =================================================================
// mma.sync fused GEMM: z0 = relu(x @ W1) @ W2, bf16 hi/lo 3-term split.
// 256 threads = 8 warps; BM=256 (warp = 32 rows x 64 cols); K chunks of 64.
// smem rows padded to 144B for conflict-free ldmatrix.
// =================================================================
#define GM_AHI 0
#define GM_ALO 36864
#define GM_BHI 73728
#define GM_BLO 82944
#define GM_SMEM 92160

__global__ __launch_bounds__(256) void gemm_mma(
    const float* __restrict__ X, const float* __restrict__ W1,
    const float* __restrict__ W2, float* __restrict__ Z0, int n)
{
    extern __shared__ char smc[];
    const uint32_t sb = smem_u32(smc);
    const int tid = threadIdx.x;
    const int wid = tid >> 5;
    const int l   = tid & 31;
    const int bm  = blockIdx.x * 256;
    const int wr  = wid * 32;

    // ldmatrix lane offsets
    const int arow = (l & 7) + ((l >> 3) & 1) * 8;       // 0..15
    const uint32_t akb = ((l >> 4) & 1) * 16;            // k byte offset
    const uint32_t aoff0 = (uint32_t)(wr + arow) * 144 + akb;
    const uint32_t aoff1 = (uint32_t)(wr + 16 + arow) * 144 + akb;
    const uint32_t boff  = (uint32_t)arow * 144 + akb;   // same pattern for B

    float acc[2][8][4];
#pragma unroll
    for (int am = 0; am < 2; am++)
#pragma unroll
        for (int na = 0; na < 8; na++)
#pragma unroll
            for (int q = 0; q < 4; q++) acc[am][na][q] = 0.f;

    // ---- phase 1: h = x @ W1, 8 chunks of K=64 ----
    for (int c = 0; c < 8; c++) {
        // A chunk: 256 rows x 64 k fp32 -> bf16 hi/lo
#pragma unroll
        for (int it = 0; it < 16; it++) {
            int idx = it * 256 + tid;     // 0..4095
            int r   = idx >> 4;
            int c4  = idx & 15;
            int row = bm + r;
            float4 v = make_float4(0.f, 0.f, 0.f, 0.f);
            if (row < n)
                v = *reinterpret_cast<const float4*>(X + (size_t)row * NFEAT + c * 64 + c4 * 4);
            uint32_t h0 = pkbf2(v.x, v.y), h1 = pkbf2(v.z, v.w);
            __nv_bfloat162 bh0 = *reinterpret_cast<__nv_bfloat162*>(&h0);
            __nv_bfloat162 bh1 = *reinterpret_cast<__nv_bfloat162*>(&h1);
            float2 f0 = __bfloat1622float2(bh0);
            float2 f1 = __bfloat1622float2(bh1);
            uint32_t l0 = pkbf2(v.x - f0.x, v.y - f0.y);
            uint32_t l1 = pkbf2(v.z - f1.x, v.w - f1.y);
            uint32_t off = (uint32_t)r * 144 + c4 * 8;
            *reinterpret_cast<uint2*>(smc + GM_AHI + off) = make_uint2(h0, h1);
            *reinterpret_cast<uint2*>(smc + GM_ALO + off) = make_uint2(l0, l1);
        }
        // B chunk: W1 rows c*64..+63, 64x64
#pragma unroll
        for (int it = 0; it < 4; it++) {
            int idx = it * 256 + tid;     // 0..1023
            int k   = idx >> 4;
            int c4  = idx & 15;
            float4 v = *reinterpret_cast<const float4*>(W1 + (size_t)(c * 64 + k) * HID + c4 * 4);
            uint32_t h0 = pkbf2(v.x, v.y), h1 = pkbf2(v.z, v.w);
            __nv_bfloat162 bh0 = *reinterpret_cast<__nv_bfloat162*>(&h0);
            __nv_bfloat162 bh1 = *reinterpret_cast<__nv_bfloat162*>(&h1);
            float2 f0 = __bfloat1622float2(bh0);
            float2 f1 = __bfloat1622float2(bh1);
            uint32_t l0 = pkbf2(v.x - f0.x, v.y - f0.y);
            uint32_t l1 = pkbf2(v.z - f1.x, v.w - f1.y);
            uint32_t off = (uint32_t)k * 144 + c4 * 8;
            *reinterpret_cast<uint2*>(smc + GM_BHI + off) = make_uint2(h0, h1);
            *reinterpret_cast<uint2*>(smc + GM_BLO + off) = make_uint2(l0, l1);
        }
        __syncthreads();

#pragma unroll
        for (int s = 0; s < 4; s++) {
            uint32_t ah0[4], ah1[4], al0[4], al1[4];
            ldsm_x4(ah0, sb + GM_AHI + aoff0 + s * 32);
            ldsm_x4(ah1, sb + GM_AHI + aoff1 + s * 32);
            ldsm_x4(al0, sb + GM_ALO + aoff0 + s * 32);
            ldsm_x4(al1, sb + GM_ALO + aoff1 + s * 32);
            uint32_t bh[8][2], bl[8][2];
#pragma unroll
            for (int p = 0; p < 4; p++) {
                uint32_t r4[4];
                ldsm_x4_t(r4, sb + GM_BHI + s * 2304 + p * 32 + boff);
                bh[2 * p][0] = r4[0]; bh[2 * p][1] = r4[1];
                bh[2 * p + 1][0] = r4[2]; bh[2 * p + 1][1] = r4[3];
                ldsm_x4_t(r4, sb + GM_BLO + s * 2304 + p * 32 + boff);
                bl[2 * p][0] = r4[0]; bl[2 * p][1] = r4[1];
                bl[2 * p + 1][0] = r4[2]; bl[2 * p + 1][1] = r4[3];
            }
#pragma unroll
            for (int na = 0; na < 8; na++) {
                mma_bf16(acc[0][na], ah0, bh[na]);
                mma_bf16(acc[1][na], ah1, bh[na]);
                mma_bf16(acc[0][na], al0, bh[na]);
                mma_bf16(acc[1][na], al1, bh[na]);
                mma_bf16(acc[0][na], ah0, bl[na]);
                mma_bf16(acc[1][na], ah1, bl[na]);
            }
        }
        __syncthreads();
    }

    // ---- phase 2: z0 = relu(h) @ W2 ----
    // h lives in acc; convert to A fragments (relu + hi/lo) in registers.
    uint32_t a2h[2][4][4], a2l[2][4][4];
#pragma unroll
    for (int am = 0; am < 2; am++)
#pragma unroll
        for (int s = 0; s < 4; s++) {
            float v00 = fmaxf(acc[am][2 * s][0], 0.f);
            float v01 = fmaxf(acc[am][2 * s][1], 0.f);
            float v02 = fmaxf(acc[am][2 * s][2], 0.f);
            float v03 = fmaxf(acc[am][2 * s][3], 0.f);
            float v10 = fmaxf(acc[am][2 * s + 1][0], 0.f);
            float v11 = fmaxf(acc[am][2 * s + 1][1], 0.f);
            float v12 = fmaxf(acc[am][2 * s + 1][2], 0.f);
            float v13 = fmaxf(acc[am][2 * s + 1][3], 0.f);
            uint32_t h;
            h = pkbf2(v00, v01); a2h[am][s][0] = h;
            { __nv_bfloat162 b = *reinterpret_cast<__nv_bfloat162*>(&h); float2 f = __bfloat1622float2(b);
              a2l[am][s][0] = pkbf2(v00 - f.x, v01 - f.y); }
            h = pkbf2(v02, v03); a2h[am][s][1] = h;
            { __nv_bfloat162 b = *reinterpret_cast<__nv_bfloat162*>(&h); float2 f = __bfloat1622float2(b);
              a2l[am][s][1] = pkbf2(v02 - f.x, v03 - f.y); }
            h = pkbf2(v10, v11); a2h[am][s][2] = h;
            { __nv_bfloat162 b = *reinterpret_cast<__nv_bfloat162*>(&h); float2 f = __bfloat1622float2(b);
              a2l[am][s][2] = pkbf2(v10 - f.x, v11 - f.y); }
            h = pkbf2(v12, v13); a2h[am][s][3] = h;
            { __nv_bfloat162 b = *reinterpret_cast<__nv_bfloat162*>(&h); float2 f = __bfloat1622float2(b);
              a2l[am][s][3] = pkbf2(v12 - f.x, v13 - f.y); }
        }

    // zero accumulators for phase 2
#pragma unroll
    for (int am = 0; am < 2; am++)
#pragma unroll
        for (int na = 0; na < 8; na++)
#pragma unroll
            for (int q = 0; q < 4; q++) acc[am][na][q] = 0.f;

    // load W2 into B smem (overwrites W1 chunk tiles)
#pragma unroll
    for (int it = 0; it < 4; it++) {
        int idx = it * 256 + tid;
        int k   = idx >> 4;
        int c4  = idx & 15;
        float4 v = *reinterpret_cast<const float4*>(W2 + (size_t)k * NCLASS + c4 * 4);
        uint32_t h0 = pkbf2(v.x, v.y), h1 = pkbf2(v.z, v.w);
        __nv_bfloat162 bh0 = *reinterpret_cast<__nv_bfloat162*>(&h0);
        __nv_bfloat162 bh1 = *reinterpret_cast<__nv_bfloat162*>(&h1);
        float2 f0 = __bfloat1622float2(bh0);
        float2 f1 = __bfloat1622float2(bh1);
        uint32_t l0 = pkbf2(v.x - f0.x, v.y - f0.y);
        uint32_t l1 = pkbf2(v.z - f1.x, v.w - f1.y);
        uint32_t off = (uint32_t)k * 144 + c4 * 8;
        *reinterpret_cast<uint2*>(smc + GM_BHI + off) = make_uint2(h0, h1);
        *reinterpret_cast<uint2*>(smc + GM_BLO + off) = make_uint2(l0, l1);
    }
    __syncthreads();

#pragma unroll
    for (int s = 0; s < 4; s++) {
        uint32_t bh[8][2], bl[8][2];
#pragma unroll
        for (int p = 0; p < 4; p++) {
            uint32_t r4[4];
            ldsm_x4_t(r4, sb + GM_BHI + s * 2304 + p * 32 + boff);
            bh[2 * p][0] = r4[0]; bh[2 * p][1] = r4[1];
            bh[2 * p + 1][0] = r4[2]; bh[2 * p + 1][1] = r4[3];
            ldsm_x4_t(r4, sb + GM_BLO + s * 2304 + p * 32 + boff);
            bl[2 * p][0] = r4[0]; bl[2 * p][1] = r4[1];
            bl[2 * p + 1][0] = r4[2]; bl[2 * p + 1][1] = r4[3];
        }
#pragma unroll
        for (int na = 0; na < 8; na++) {
            mma_bf16(acc[0][na], a2h[0][s], bh[na]);
            mma_bf16(acc[1][na], a2h[1][s], bh[na]);
            mma_bf16(acc[0][na], a2l[0][s], bh[na]);
            mma_bf16(acc[1][na], a2l[1][s], bh[na]);
            mma_bf16(acc[0][na], a2h[0][s], bl[na]);
            mma_bf16(acc[1][na], a2h[1][s], bl[na]);
        }
    }

    // store z0
#pragma unroll
    for (int am = 0; am < 2; am++) {
        int r0 = bm + wr + am * 16 + (l >> 2);
        int col = (l & 3) * 2;
#pragma unroll
        for (int na = 0; na < 8; na++) {
            if (r0 < n)
                *reinterpret_cast<float2*>(Z0 + (size_t)r0 * NCLASS + na * 8 + col) =
                    make_float2(acc[am][na][0], acc[am][na][1]);
            if (r0 + 8 < n)
                *reinterpret_cast<float2*>(Z0 + (size_t)(r0 + 8) * NCLASS + na * 8 + col) =
                    make_float2(acc[am][na][2], acc[am][na][3]);
        }
    }
}

// =================================================================
// CSR construction
// =================================================================
__global__ __launch_bounds__(256) void zero_hist(int* __restrict__ cnt, int n)
{
    int i = blockIdx.x * 256 + threadIdx.x;
    if (i < n) cnt[i] = 0;
}

__global__ __launch_bounds__(256) void hist_dst(
    const int* __restrict__ dst, int* __restrict__ cnt, int e)
{
    int i = blockIdx.x * 256 + threadIdx.x;
    if (i < e) atomicAdd(&cnt[dst[i]], 1);
}

__global__ __launch_bounds__(SCAN_BLK) void scan1(
    const int* __restrict__ cnt, int* __restrict__ rowptr,
    int* __restrict__ bsums, int n)
{
    __shared__ int sh[SCAN_BLK];
    int t = threadIdx.x;
    int i = blockIdx.x * SCAN_BLK + t;
    int v = (i < n) ? cnt[i] : 0;
    sh[t] = v;
    __syncthreads();
#pragma unroll
    for (int off = 1; off < SCAN_BLK; off <<= 1) {
        int x = (t >= off) ? sh[t - off] : 0;
        __syncthreads();
        sh[t] += x;
        __syncthreads();
    }
    int incl = sh[t];
    if (i < n) rowptr[i] = incl - v;
    if (t == SCAN_BLK - 1) bsums[blockIdx.x] = incl;
}

__global__ __launch_bounds__(128) void scan2(int* __restrict__ bsums, int nb)
{
    __shared__ int sh[128];
    int t = threadIdx.x;
    int v = (t < nb) ? bsums[t] : 0;
    sh[t] = v;
    __syncthreads();
#pragma unroll
    for (int off = 1; off < 128; off <<= 1) {
        int x = (t >= off) ? sh[t - off] : 0;
        __syncthreads();
        sh[t] += x;
        __syncthreads();
    }
    if (t < nb) bsums[t] = sh[t] - v;
}

__global__ __launch_bounds__(256) void scan3(
    int* __restrict__ rowptr, int* __restrict__ cursor,
    const int* __restrict__ bsums, int n, int e)
{
    int i = blockIdx.x * 256 + threadIdx.x;
    if (i < n) {
        int v = rowptr[i] + bsums[i >> 10];
        rowptr[i] = v;
        cursor[i] = v;
    }
    if (i == n) rowptr[n] = e;
}

__global__ __launch_bounds__(256) void build_edges(
    const int* __restrict__ src, const int* __restrict__ dst,
    const float* __restrict__ ew, int* __restrict__ cursor,
    int2* __restrict__ edges, int e)
{
    int i = blockIdx.x * 256 + threadIdx.x;
    if (i < e) {
        int d = dst[i];
        int pos = atomicAdd(&cursor[d], 1);
        edges[pos] = make_int2(src[i], __float_as_int(ew[i]));
    }
}

// =================================================================
// gather (scaled fp16 pipeline): one warp per dst node.
// =================================================================
__device__ __forceinline__ void load_row8_h(
    const __half* zin, int node, int c8, float* v)
{
    float4 raw = __ldg(reinterpret_cast<const float4*>(zin + (size_t)node * NCLASS) + c8);
    const __half2* h = reinterpret_cast<const __half2*>(&raw);
#pragma unroll
    for (int j = 0; j < 4; j++) {
        float2 f = __half22float2(h[j]);
        v[2 * j]     = f.x;
        v[2 * j + 1] = f.y;
    }
}
__device__ __forceinline__ void load_row8_f(
    const float* zin, int node, int c8, float* v)
{
    const float4* p = reinterpret_cast<const float4*>(zin + (size_t)node * NCLASS);
    float4 a = __ldg(p + 2 * c8);
    float4 b = __ldg(p + 2 * c8 + 1);
    v[0] = a.x; v[1] = a.y; v[2] = a.z; v[3] = a.w;
    v[4] = b.x; v[5] = b.y; v[6] = b.z; v[7] = b.w;
}

template<bool IN_HALF, bool LAST>
__global__ __launch_bounds__(256) void gather_nodes(
    const int2* __restrict__ edges, const int* __restrict__ rowptr,
    const void* __restrict__ zin_v, const float* __restrict__ z0,
    void* __restrict__ zout_v, float c1, float c0, int n)
{
    int warp = (blockIdx.x * 256 + threadIdx.x) >> 5;
    if (warp >= n) return;
    int lane = threadIdx.x & 31;
    int sub  = lane >> 3;
    int c8   = lane & 7;

    const __half* zin_h = (const __half*)zin_v;
    const float*  zin_f = (const float*)zin_v;

    int beg = __ldg(&rowptr[warp]);
    int end = __ldg(&rowptr[warp + 1]);

    float acc[8];
#pragma unroll
    for (int j = 0; j < 8; j++) acc[j] = 0.f;

    int i = beg + sub;
    for (; i + 4 < end; i += 8) {
        int2 e0 = __ldg(&edges[i]);
        int2 e1 = __ldg(&edges[i + 4]);
        float v0[8], v1[8];
        if (IN_HALF) { load_row8_h(zin_h, e0.x, c8, v0); load_row8_h(zin_h, e1.x, c8, v1); }
        else         { load_row8_f(zin_f, e0.x, c8, v0); load_row8_f(zin_f, e1.x, c8, v1); }
        float w0 = __int_as_float(e0.y);
        float w1 = __int_as_float(e1.y);
#pragma unroll
        for (int j = 0; j < 8; j++) acc[j] = fmaf(w0, v0[j], acc[j]);
#pragma unroll
        for (int j = 0; j < 8; j++) acc[j] = fmaf(w1, v1[j], acc[j]);
    }
    for (; i < end; i += 4) {
        int2 e0 = __ldg(&edges[i]);
        float v0[8];
        if (IN_HALF) load_row8_h(zin_h, e0.x, c8, v0);
        else         load_row8_f(zin_f, e0.x, c8, v0);
        float w0 = __int_as_float(e0.y);
#pragma unroll
        for (int j = 0; j < 8; j++) acc[j] = fmaf(w0, v0[j], acc[j]);
    }

    const unsigned FULL = 0xFFFFFFFFu;
#pragma unroll
    for (int j = 0; j < 8; j++) {
        acc[j] += __shfl_xor_sync(FULL, acc[j], 8);
        acc[j] += __shfl_xor_sync(FULL, acc[j], 16);
    }

    float z0v[8];
    load_row8_f(z0, warp, c8, z0v);
    float o[8];
#pragma unroll
    for (int j = 0; j < 8; j++) o[j] = fmaf(c0, z0v[j], c1 * acc[j]);

    if (!LAST) {
        if (sub == 0) {
            __half2 h[4];
#pragma unroll
            for (int j = 0; j < 4; j++)
                h[j] = __floats2half2_rn(o[2 * j], o[2 * j + 1]);
            __half* zo = (__half*)zout_v;
            *(reinterpret_cast<float4*>(zo + (size_t)warp * NCLASS) + c8) =
                *reinterpret_cast<float4*>(h);
        }
    } else {
        float m = o[0];
#pragma unroll
        for (int j = 1; j < 8; j++) m = fmaxf(m, o[j]);
#pragma unroll
        for (int off = 1; off < 8; off <<= 1)
            m = fmaxf(m, __shfl_xor_sync(FULL, m, off));
        float s = 0.f;
#pragma unroll
        for (int j = 0; j < 8; j++) s += __expf(o[j] - m);
#pragma unroll
        for (int off = 1; off < 8; off <<= 1)
            s += __shfl_xor_sync(FULL, s, off);
        float l = m + __logf(s);
        if (sub == 0) {
            float* zo = (float*)zout_v;
            float4 r0 = make_float4(o[0] - l, o[1] - l, o[2] - l, o[3] - l);
            float4 r1 = make_float4(o[4] - l, o[5] - l, o[6] - l, o[7] - l);
            float4* p = reinterpret_cast<float4*>(zo + (size_t)warp * NCLASS);
            p[2 * c8]     = r0;
            p[2 * c8 + 1] = r1;
        }
    }
}

// =================================================================
// launch
// =================================================================
extern "C" void kernel_launch(void* const* d_in, const int* in_sizes, int n_in,
                              void* d_out, int out_size)
{
    const float* x   = (const float*)d_in[0];
    const int*   ei  = (const int*)  d_in[1];
    const float* ew  = (const float*)d_in[2];
    const float* W1  = (const float*)d_in[3];
    const float* W2  = (const float*)d_in[4];
    float*       out = (float*)d_out;

    const int n = in_sizes[0] / NFEAT;
    const int e = in_sizes[2];
    const int* src = ei;
    const int* dst = ei + e;

    float*  z0  = nullptr; cudaGetSymbolAddress((void**)&z0,  g_z0);
    __half* ya  = nullptr; cudaGetSymbolAddress((void**)&ya,  g_ya);
    __half* yb  = nullptr; cudaGetSymbolAddress((void**)&yb,  g_yb);
    int*    rp  = nullptr; cudaGetSymbolAddress((void**)&rp,  g_rowptr);
    int*    cur = nullptr; cudaGetSymbolAddress((void**)&cur, g_cursor);
    int*    bs  = nullptr; cudaGetSymbolAddress((void**)&bs,  g_bsums);
    int2*   edg = nullptr; cudaGetSymbolAddress((void**)&edg, g_edges);

    static cudaStream_t sG = nullptr;
    static cudaEvent_t  evF = nullptr, evG = nullptr;
    if (sG == nullptr) {
        cudaStreamCreateWithFlags(&sG, cudaStreamNonBlocking);
        cudaEventCreateWithFlags(&evF, cudaEventDisableTiming);
        cudaEventCreateWithFlags(&evG, cudaEventDisableTiming);
        cudaFuncSetAttribute(gemm_mma,
            cudaFuncAttributeMaxDynamicSharedMemorySize, GM_SMEM);
    }

    // ---- fork: tensor-core GEMM on side stream ----
    cudaEventRecord(evF, 0);
    cudaStreamWaitEvent(sG, evF, 0);
    gemm_mma<<<(n + 255) / 256, 256, GM_SMEM, sG>>>(x, W1, W2, z0, n);
    cudaEventRecord(evG, sG);

    // ---- CSR build on capture stream ----
    zero_hist<<<(n + 255) / 256, 256>>>(cur, n);
    hist_dst<<<(e + 255) / 256, 256>>>(dst, cur, e);
    int nb = (n + SCAN_BLK - 1) / SCAN_BLK;
    scan1<<<nb, SCAN_BLK>>>(cur, rp, bs, n);
    scan2<<<1, 128>>>(bs, nb);
    scan3<<<(n + 256) / 256, 256>>>(rp, cur, bs, n, e);
    build_edges<<<(e + 255) / 256, 256>>>(src, dst, ew, cur, edg, e);

    // ---- join ----
    cudaStreamWaitEvent(0, evG, 0);

    // ---- APPNP, scaled-fp16 pipeline ----
    const float S = 16.0f;
    const int gblocks = (n * 32 + 255) / 256;

    gather_nodes<false, false><<<gblocks, 256>>>(
        edg, rp, z0, z0, ya, 1.0f / S, ALPHA / S, n);

    __half* bufs[2] = { ya, yb };
    float pw = S * S;
    for (int t = 1; t <= 8; t++) {
        __half* zin  = bufs[(t + 1) & 1];
        __half* zout = bufs[t & 1];
        gather_nodes<true, false><<<gblocks, 256>>>(
            edg, rp, zin, z0, zout, 1.0f / S, ALPHA / pw, n);
        pw *= S;
    }

    float S9 = 1.0f;
    for (int k = 0; k < 9; k++) S9 *= S;
    gather_nodes<true, true><<<gblocks, 256>>>(
        edg, rp, bufs[1], z0, out, S9, ALPHA, n);
}